// round 8
// baseline (speedup 1.0000x reference)
#include <cuda_runtime.h>

// Delta differential encoding with residual carry + floor quantization.
// x: [B=32, C=2048, T=512] float32, contiguous in T.
// 16 rows per single-warp block -> 4096 warps (27.7/SM, occ ~43%) to fill
// issue/latency gaps that capped DRAM at 60% with 2048 warps.
// Memory phases use all 32 lanes (coalesced cp.async in, float4 out);
// carry chains run on lanes 0-15. Depth-3 pipeline, in-place output,
// speculative chain.

#define SCALE 64.0f
#define INV_SCALE (1.0f / 64.0f)
#define T_LEN 512
#define N_ROWS (32 * 2048)

#define RPW 16             // rows per warp (one per lane 0..15)
#define RPB 32             // 1 warp per block
#define CHUNK 32           // floats per row per chunk (= one 128B line)
#define PAD 36             // padded row stride in floats (conflict-free, 16B aligned)
#define NCHUNK (T_LEN / CHUNK)   // 16
#define F4_PER_LANE 4            // 16 rows * 8 float4 / 32 lanes
#define DEPTH 3

#define BUF_FLOATS (RPW * PAD)           // one buffer (576 floats)
#define SMEM_FLOATS (DEPTH * BUF_FLOATS)
#define SMEM_BYTES (SMEM_FLOATS * 4)     // 6912 B/block -> 28 blocks/SM fits

__global__ void __launch_bounds__(RPB) delta_kernel(
    const float* __restrict__ x,
    const float* __restrict__ thr_in,
    float* __restrict__ out)
{
    extern __shared__ float smem[];

    const int lane = threadIdx.x & 31;

    float* bufs[DEPTH] = { smem, smem + BUF_FLOATS, smem + 2 * BUF_FLOATS };

    const size_t rowbase = (size_t)blockIdx.x * RPW;
    const float* gx = x   + rowbase * T_LEN;
    float*       gy = out + rowbase * T_LEN;

    const float thr = fmaxf(__ldg(thr_in), INV_SCALE);

    // Coalesced async load of one chunk: 8 consecutive lanes cover one row's
    // 128B line; warp covers 4 rows per iteration, 4 iterations = 16 rows.
    auto issue_chunk = [&](float* sbuf, int k) {
        const float* gsrc = gx + (size_t)k * CHUNK;
#pragma unroll
        for (int i = 0; i < F4_PER_LANE; ++i) {
            int f   = lane + 32 * i;    // 0..127
            int row = f >> 3;           // 0..15
            int t4  = f & 7;            // 0..7
            const float* src = gsrc + (size_t)row * T_LEN + t4 * 4;
            unsigned saddr = (unsigned)__cvta_generic_to_shared(sbuf + row * PAD + t4 * 4);
            asm volatile("cp.async.cg.shared.global [%0], [%1], 16;"
                         :: "r"(saddr), "l"(src));
        }
        asm volatile("cp.async.commit_group;");
    };

    // Prologue: fill two stages.
    issue_chunk(bufs[0], 0);
    issue_chunk(bufs[1], 1);

    float pre = 0.0f;  // x[t-1] at chunk boundary
    float r   = 0.0f;  // residual carry at chunk boundary

#pragma unroll 1
    for (int k = 0; k < NCHUNK; ++k) {
        float* sbuf = bufs[k % DEPTH];

        if (k + 2 < NCHUNK) {
            issue_chunk(bufs[(k + 2) % DEPTH], k + 2);
            asm volatile("cp.async.wait_group 2;");
        } else if (k + 1 < NCHUNK) {
            asm volatile("cp.async.wait_group 1;");
        } else {
            asm volatile("cp.async.wait_group 0;");
        }
        __syncwarp();   // chunk k visible warp-wide

        // ---- per-row sequential work: lanes 0..15 own one row each ----
        if (lane < RPW) {
            float* myrow = sbuf + lane * PAD;
            float a[CHUNK];
#pragma unroll
            for (int j4 = 0; j4 < CHUNK / 4; ++j4) {
                float4 v = *reinterpret_cast<const float4*>(myrow + 4 * j4);
                a[4 * j4 + 0] = v.x;
                a[4 * j4 + 1] = v.y;
                a[4 * j4 + 2] = v.z;
                a[4 * j4 + 3] = v.w;
            }
            float dx[CHUNK];
            dx[0] = a[0] - pre;
#pragma unroll
            for (int j = 1; j < CHUNK; ++j) dx[j] = a[j] - a[j - 1];
            pre = a[CHUNK - 1];

            // Speculative carry chain: ~8 cyc/element critical path.
            float d = dx[0] + r;
            float o4s[CHUNK];
#pragma unroll
            for (int j = 0; j < CHUNK; ++j) {
                bool  keep = fabsf(d) >= thr;
                float y    = keep ? d : 0.0f;
                o4s[j]     = floorf(y * SCALE) * INV_SCALE;
                if (j + 1 < CHUNK) {
                    float dc = dx[j + 1] + d;   // starts as soon as d resolves
                    d = keep ? dx[j + 1] : dc;  // FSEL, pred-as-data
                } else {
                    r = keep ? 0.0f : d;
                }
            }

            // Write results back in place.
#pragma unroll
            for (int j4 = 0; j4 < CHUNK / 4; ++j4) {
                float4 o4;
                o4.x = o4s[4 * j4 + 0];
                o4.y = o4s[4 * j4 + 1];
                o4.z = o4s[4 * j4 + 2];
                o4.w = o4s[4 * j4 + 3];
                *reinterpret_cast<float4*>(myrow + 4 * j4) = o4;
            }
        }
        __syncwarp();   // outputs in place before cooperative store

        // ---- coalesced cooperative store of this chunk (all 32 lanes) ----
        float* gdst = gy + (size_t)k * CHUNK;
#pragma unroll
        for (int i = 0; i < F4_PER_LANE; ++i) {
            int f   = lane + 32 * i;
            int row = f >> 3;
            int t4  = f & 7;
            *reinterpret_cast<float4*>(gdst + (size_t)row * T_LEN + t4 * 4) =
                *reinterpret_cast<const float4*>(sbuf + row * PAD + t4 * 4);
        }
        __syncwarp();   // store reads done before chunk k+3's cp.async reuses sbuf
    }
}

extern "C" void kernel_launch(void* const* d_in, const int* in_sizes, int n_in,
                              void* d_out, int out_size)
{
    const float* x   = (const float*)d_in[0];
    const float* thr = (const float*)d_in[1];
    float* out       = (float*)d_out;

    const int blocks = N_ROWS / RPW;   // 4096 one-warp blocks
    delta_kernel<<<blocks, RPB, SMEM_BYTES>>>(x, thr, out);
}

// round 9
// speedup vs baseline: 1.0306x; 1.0306x over previous
#include <cuda_runtime.h>

// Delta differential encoding with residual carry + floor quantization.
// x: [B=32, C=2048, T=512] float32, contiguous in T.
// At the chip memory-system floor (~44us: 512MB of L2-face traffic at the
// ~6300 B/cyc LTS cap). 4096 single-warp blocks (1 wave, 1.3% imbalance),
// warp-private smem staging, depth-3 cp.async pipeline, in-place output,
// speculative carry chain. This round: evict-first (.cs) output stores so
// write lines drain from L2 instead of competing with read fills.

#define SCALE 64.0f
#define INV_SCALE (1.0f / 64.0f)
#define T_LEN 512
#define N_ROWS (32 * 2048)

#define RPW 16             // rows per warp (one per lane 0..15)
#define RPB 32             // 1 warp per block
#define CHUNK 32           // floats per row per chunk (= one 128B line)
#define PAD 36             // padded row stride in floats (conflict-free, 16B aligned)
#define NCHUNK (T_LEN / CHUNK)   // 16
#define F4_PER_LANE 4            // 16 rows * 8 float4 / 32 lanes
#define DEPTH 3

#define BUF_FLOATS (RPW * PAD)           // one buffer (576 floats)
#define SMEM_FLOATS (DEPTH * BUF_FLOATS)
#define SMEM_BYTES (SMEM_FLOATS * 4)     // 6912 B/block -> 28 blocks/SM, single wave

__device__ __forceinline__ void stg128_cs(float* p, float4 v) {
    asm volatile("st.global.cs.v4.f32 [%0], {%1,%2,%3,%4};"
                 :: "l"(p), "f"(v.x), "f"(v.y), "f"(v.z), "f"(v.w) : "memory");
}

__global__ void __launch_bounds__(RPB) delta_kernel(
    const float* __restrict__ x,
    const float* __restrict__ thr_in,
    float* __restrict__ out)
{
    extern __shared__ float smem[];

    const int lane = threadIdx.x & 31;

    float* bufs[DEPTH] = { smem, smem + BUF_FLOATS, smem + 2 * BUF_FLOATS };

    const size_t rowbase = (size_t)blockIdx.x * RPW;
    const float* gx = x   + rowbase * T_LEN;
    float*       gy = out + rowbase * T_LEN;

    const float thr = fmaxf(__ldg(thr_in), INV_SCALE);

    // Coalesced async load of one chunk: 8 consecutive lanes cover one row's
    // 128B line; 4 iterations cover all 16 rows.
    auto issue_chunk = [&](float* sbuf, int k) {
        const float* gsrc = gx + (size_t)k * CHUNK;
#pragma unroll
        for (int i = 0; i < F4_PER_LANE; ++i) {
            int f   = lane + 32 * i;    // 0..127
            int row = f >> 3;           // 0..15
            int t4  = f & 7;            // 0..7
            const float* src = gsrc + (size_t)row * T_LEN + t4 * 4;
            unsigned saddr = (unsigned)__cvta_generic_to_shared(sbuf + row * PAD + t4 * 4);
            asm volatile("cp.async.cg.shared.global [%0], [%1], 16;"
                         :: "r"(saddr), "l"(src));
        }
        asm volatile("cp.async.commit_group;");
    };

    // Prologue: fill two stages.
    issue_chunk(bufs[0], 0);
    issue_chunk(bufs[1], 1);

    float pre = 0.0f;  // x[t-1] at chunk boundary
    float r   = 0.0f;  // residual carry at chunk boundary

#pragma unroll 1
    for (int k = 0; k < NCHUNK; ++k) {
        float* sbuf = bufs[k % DEPTH];

        if (k + 2 < NCHUNK) {
            issue_chunk(bufs[(k + 2) % DEPTH], k + 2);
            asm volatile("cp.async.wait_group 2;");
        } else if (k + 1 < NCHUNK) {
            asm volatile("cp.async.wait_group 1;");
        } else {
            asm volatile("cp.async.wait_group 0;");
        }
        __syncwarp();   // chunk k visible warp-wide

        // ---- per-row sequential work: lanes 0..15 own one row each ----
        if (lane < RPW) {
            float* myrow = sbuf + lane * PAD;
            float a[CHUNK];
#pragma unroll
            for (int j4 = 0; j4 < CHUNK / 4; ++j4) {
                float4 v = *reinterpret_cast<const float4*>(myrow + 4 * j4);
                a[4 * j4 + 0] = v.x;
                a[4 * j4 + 1] = v.y;
                a[4 * j4 + 2] = v.z;
                a[4 * j4 + 3] = v.w;
            }
            float dx[CHUNK];
            dx[0] = a[0] - pre;
#pragma unroll
            for (int j = 1; j < CHUNK; ++j) dx[j] = a[j] - a[j - 1];
            pre = a[CHUNK - 1];

            // Speculative carry chain: ~8 cyc/element critical path.
            float d = dx[0] + r;
            float o4s[CHUNK];
#pragma unroll
            for (int j = 0; j < CHUNK; ++j) {
                bool  keep = fabsf(d) >= thr;
                float y    = keep ? d : 0.0f;
                o4s[j]     = floorf(y * SCALE) * INV_SCALE;
                if (j + 1 < CHUNK) {
                    float dc = dx[j + 1] + d;   // starts as soon as d resolves
                    d = keep ? dx[j + 1] : dc;  // FSEL, pred-as-data
                } else {
                    r = keep ? 0.0f : d;
                }
            }

            // Write results back in place.
#pragma unroll
            for (int j4 = 0; j4 < CHUNK / 4; ++j4) {
                float4 o4;
                o4.x = o4s[4 * j4 + 0];
                o4.y = o4s[4 * j4 + 1];
                o4.z = o4s[4 * j4 + 2];
                o4.w = o4s[4 * j4 + 3];
                *reinterpret_cast<float4*>(myrow + 4 * j4) = o4;
            }
        }
        __syncwarp();   // outputs in place before cooperative store

        // ---- coalesced cooperative store (evict-first: stream writes out) ----
        float* gdst = gy + (size_t)k * CHUNK;
#pragma unroll
        for (int i = 0; i < F4_PER_LANE; ++i) {
            int f   = lane + 32 * i;
            int row = f >> 3;
            int t4  = f & 7;
            stg128_cs(gdst + (size_t)row * T_LEN + t4 * 4,
                      *reinterpret_cast<const float4*>(sbuf + row * PAD + t4 * 4));
        }
        __syncwarp();   // store reads done before chunk k+3's cp.async reuses sbuf
    }
}

extern "C" void kernel_launch(void* const* d_in, const int* in_sizes, int n_in,
                              void* d_out, int out_size)
{
    const float* x   = (const float*)d_in[0];
    const float* thr = (const float*)d_in[1];
    float* out       = (float*)d_out;

    const int blocks = N_ROWS / RPW;   // 4096 one-warp blocks
    delta_kernel<<<blocks, RPB, SMEM_BYTES>>>(x, thr, out);
}